// round 13
// baseline (speedup 1.0000x reference)
#include <cuda_runtime.h>
#include <math.h>
#include <stdint.h>

// Problem constants
#define BB   4
#define NN   2000
#define KKN  30
#define DD   128
#define DIN  256
#define HH   4
#define ROWS (BB*NN)           // 8000

#define SCALE 0.17677669529663687f   // 1/sqrt(32)

#define EPITCH 260             // padded E row pitch (floats): conflict-free banks
#define QPITCH 260             // padded Q row pitch

// Scratch (static device globals: no runtime allocation)
__device__ float g_Qp  [(size_t)ROWS*HH*DIN];  // 32 MB  per-head K-projected query
__device__ float g_Eagg[(size_t)ROWS*HH*DIN];  // 32 MB  softmax-weighted E aggregate
__device__ float g_hu  [(size_t)ROWS*DD];      //  4 MB  per-head V projection

// ---------------------------------------------------------------------------
// Kernel QQp (fused): per head h, 64-row block.
//   Phase 1: Q_h[r][j] = sum_d hV[r][d] * WQ[h*32+j][d]     (into smem qs)
//   Phase 2: Qp[r][h*256+c] = SCALE * sum_j Q_h[r][j] * WK[h*32+j][c]
// grid (125, 4 heads), 256 threads.
// ---------------------------------------------------------------------------
__global__ __launch_bounds__(256) void kQQp(const float* __restrict__ hV,
                                            const float* __restrict__ WQ,
                                            const float* __restrict__ WK)
{
    __shared__ float as[64*33];    // hV chunk (64 x 32)
    __shared__ float bs[32*33];    // WQ chunk (32 j x 32 d)
    __shared__ float qs[64*33];    // Q_h tile (64 x 32)
    __shared__ float ws[32*65];    // WK chunk (32 j x 64 c)

    const int tid  = threadIdx.x;
    const int row0 = blockIdx.x * 64;
    const int h    = blockIdx.y;
    const int rt   = tid >> 4;   // 0..15
    const int jt   = tid & 15;   // 0..15

    // ---- Phase 1: Q_h = hV @ WQ_h^T (K=128, chunk 32), tile 64x32, acc[4][2]
    float acc[4][2] = {};
    for (int dc = 0; dc < DD; dc += 32) {
        __syncthreads();
        #pragma unroll
        for (int i = tid; i < 64*32; i += 256) {
            int r = i >> 5, c = i & 31;
            as[r*33 + c] = hV[(size_t)(row0 + r)*DD + dc + c];
        }
        #pragma unroll
        for (int i = tid; i < 32*32; i += 256) {
            int j = i >> 5, c = i & 31;
            bs[j*33 + c] = WQ[(size_t)(h*32 + j)*DD + dc + c];
        }
        __syncthreads();
        #pragma unroll
        for (int c = 0; c < 32; c++) {
            float a[4], b[2];
            #pragma unroll
            for (int m = 0; m < 4; m++) a[m] = as[(rt + 16*m)*33 + c];
            #pragma unroll
            for (int n = 0; n < 2; n++) b[n] = bs[(jt + 16*n)*33 + c];
            #pragma unroll
            for (int m = 0; m < 4; m++)
                #pragma unroll
                for (int n = 0; n < 2; n++) acc[m][n] += a[m]*b[n];
        }
    }
    __syncthreads();
    #pragma unroll
    for (int m = 0; m < 4; m++)
        #pragma unroll
        for (int n = 0; n < 2; n++)
            qs[(rt + 16*m)*33 + jt + 16*n] = acc[m][n];

    // ---- Phase 2: Qp = qs(64x32) @ WK_h(32x256), c chunked by 64, acc[4][4]
    const int ct = tid & 15;
    for (int cc = 0; cc < DIN; cc += 64) {
        __syncthreads();
        #pragma unroll
        for (int i = tid; i < 32*64; i += 256) {
            int j = i >> 6, c = i & 63;
            ws[j*65 + c] = WK[(size_t)(h*32 + j)*DIN + cc + c];
        }
        __syncthreads();

        float a2[4][4] = {};
        #pragma unroll
        for (int j = 0; j < 32; j++) {
            float a[4], b[4];
            #pragma unroll
            for (int m = 0; m < 4; m++) a[m] = qs[(rt + 16*m)*33 + j];
            #pragma unroll
            for (int n = 0; n < 4; n++) b[n] = ws[j*65 + ct + 16*n];
            #pragma unroll
            for (int m = 0; m < 4; m++)
                #pragma unroll
                for (int n = 0; n < 4; n++) a2[m][n] += a[m]*b[n];
        }
        #pragma unroll
        for (int m = 0; m < 4; m++)
            #pragma unroll
            for (int n = 0; n < 4; n++)
                g_Qp[(size_t)(row0 + rt + 16*m)*(HH*DIN) + h*DIN + cc + ct + 16*n]
                    = a2[m][n] * SCALE;
    }
}

// ---------------------------------------------------------------------------
// Kernel 2 (shuffle-free, split logits): one block per row, 256 threads.
// Logits split across two 120-thread groups (half the dot each); the partial
// combine is folded into the softmax read (one less sync + smem pass).
// ---------------------------------------------------------------------------
__global__ __launch_bounds__(256) void k2_attn(const float* __restrict__ hE,
                                               const int*   __restrict__ mask)
{
    __shared__ __align__(16) float Es[KKN*EPITCH];  // 30x260
    __shared__ __align__(16) float Qs[HH*QPITCH];   // 4x260
    __shared__ float lp[2*120];                     // partial logits
    __shared__ __align__(16) float ws[32*4];        // [k][h]
    __shared__ int   ms[32];

    const int tid = threadIdx.x;
    const int row = blockIdx.x;

    // Loads: Qp row + mask first (hide under E stream), then E tile (1920 float4)
    {
        if (tid < (HH*DIN)/4) {
            const float4* Qg = (const float4*)(g_Qp + (size_t)row * (HH*DIN));
            int h = tid >> 6, c4 = tid & 63;
            *(float4*)&Qs[h*QPITCH + c4*4] = Qg[tid];
        }
        if (tid < KKN) ms[tid] = mask[row*KKN + tid];

        const float4* Eg = (const float4*)(hE + (size_t)row * (KKN*DIN));
        #pragma unroll 4
        for (int i = tid; i < (KKN*DIN)/4; i += 256) {
            int k = i >> 6, c4 = i & 63;
            *(float4*)&Es[k*EPITCH + c4*4] = Eg[i];
        }
    }
    __syncthreads();

    // ---- logits: two groups, each thread does a 128-float private dot ----
    {
        const int grp = tid >> 7;          // 0 or 1
        const int t   = tid & 127;         // index within group
        if (t < 120) {
            const int k = t >> 2, h = t & 3;
            const float4* e4 = (const float4*)(Es + k*EPITCH) + grp*32;
            const float4* q4 = (const float4*)(Qs + h*QPITCH) + grp*32;
            float a0 = 0.f, a1 = 0.f, a2 = 0.f, a3 = 0.f;
            #pragma unroll
            for (int c = 0; c < 32; c += 4) {
                float4 e, q;
                e = e4[c+0]; q = q4[c+0]; a0 += e.x*q.x + e.y*q.y + e.z*q.z + e.w*q.w;
                e = e4[c+1]; q = q4[c+1]; a1 += e.x*q.x + e.y*q.y + e.z*q.z + e.w*q.w;
                e = e4[c+2]; q = q4[c+2]; a2 += e.x*q.x + e.y*q.y + e.z*q.z + e.w*q.w;
                e = e4[c+3]; q = q4[c+3]; a3 += e.x*q.x + e.y*q.y + e.z*q.z + e.w*q.w;
            }
            lp[grp*120 + t] = (a0 + a1) + (a2 + a3);
        }
    }
    __syncthreads();

    const int warp = tid >> 5, lane = tid & 31;

    // ---- masked softmax per head (one warp per head); combine partials here
    if (warp < HH) {
        int   m = 0;
        float v = -3.0e38f;
        if (lane < KKN) {
            m = ms[lane];
            int idx = lane*4 + warp;
            v = m ? (lp[idx] + lp[120 + idx]) : -3.0e38f;
        }
        float mx = v;
        #pragma unroll
        for (int off = 16; off; off >>= 1) mx = fmaxf(mx, __shfl_xor_sync(0xffffffffu, mx, off));
        float e   = (lane < KKN) ? expf(v - mx) : 0.f;
        float smv = e;
        #pragma unroll
        for (int off = 16; off; off >>= 1) smv += __shfl_xor_sync(0xffffffffu, smv, off);
        if (lane < KKN) ws[lane*4 + warp] = (e / smv) * (float)m;
    }
    __syncthreads();

    // ---- aggregation: Eagg[h][c] = sum_k w[k][h] * E[k][c] ----
    {
        const int c = tid;  // 0..255
        float acc0 = 0.f, acc1 = 0.f, acc2 = 0.f, acc3 = 0.f;
        #pragma unroll 5
        for (int k = 0; k < KKN; k++) {
            float4 w  = *(const float4*)&ws[k*4];
            float  ev = Es[k*EPITCH + c];
            acc0 += w.x * ev; acc1 += w.y * ev; acc2 += w.z * ev; acc3 += w.w * ev;
        }
        float* out = g_Eagg + (size_t)row * (HH*DIN);
        out[0*DIN + c] = acc0;
        out[1*DIN + c] = acc1;
        out[2*DIN + c] = acc2;
        out[3*DIN + c] = acc3;
    }
}

// ---------------------------------------------------------------------------
// Kernel 3: hu[r][h*32+j] = sum_c WV[h*32+j][c] * Eagg[r][h][c]
// 32 rows x 32 j (one head), 256 threads, acc[2][2], double-buffered.
// grid (250, 4 heads) = 1000 blocks (~6.8/SM).
// ---------------------------------------------------------------------------
__global__ __launch_bounds__(256) void k3_vproj(const float* __restrict__ WV)
{
    __shared__ float as[32*33];
    __shared__ float bs[32*33];

    const int tid  = threadIdx.x;
    const int row0 = blockIdx.x * 32;
    const int h    = blockIdx.y;
    const int rt   = tid >> 4;
    const int jt   = tid & 15;

    const float* A  = g_Eagg + (size_t)h * DIN;
    const float* Bw = WV + (size_t)h * 32 * DIN;

    float ra[4], rb[4];
    #pragma unroll
    for (int it = 0; it < 4; it++) {
        int i = tid + 256*it;
        ra[it] = A[(size_t)(row0 + (i >> 5))*(HH*DIN) + (i & 31)];
        rb[it] = Bw[(size_t)(i >> 5)*DIN + (i & 31)];
    }

    float acc[2][2] = {};
    for (int cc = 0; cc < DIN; cc += 32) {
        __syncthreads();
        #pragma unroll
        for (int it = 0; it < 4; it++) {
            int i = tid + 256*it;
            as[(i >> 5)*33 + (i & 31)] = ra[it];
            bs[(i >> 5)*33 + (i & 31)] = rb[it];
        }
        __syncthreads();
        if (cc + 32 < DIN) {
            #pragma unroll
            for (int it = 0; it < 4; it++) {
                int i = tid + 256*it;
                ra[it] = A[(size_t)(row0 + (i >> 5))*(HH*DIN) + cc + 32 + (i & 31)];
                rb[it] = Bw[(size_t)(i >> 5)*DIN + cc + 32 + (i & 31)];
            }
        }
        #pragma unroll
        for (int c = 0; c < 32; c++) {
            float a[2], b[2];
            #pragma unroll
            for (int m = 0; m < 2; m++) a[m] = as[(rt + 16*m)*33 + c];
            #pragma unroll
            for (int n = 0; n < 2; n++) b[n] = bs[(jt + 16*n)*33 + c];
            #pragma unroll
            for (int m = 0; m < 2; m++)
                #pragma unroll
                for (int n = 0; n < 2; n++) acc[m][n] += a[m]*b[n];
        }
    }
    #pragma unroll
    for (int m = 0; m < 2; m++)
        #pragma unroll
        for (int n = 0; n < 2; n++)
            g_hu[(size_t)(row0 + rt + 16*m)*DD + h*32 + jt + 16*n] = acc[m][n];
}

// ---------------------------------------------------------------------------
// Kernel 4: out[r][o] = sum_d hu[r][d] * WO[o][d]
// 32 rows x 32 cols, grid (250, 4) = 1000 blocks, acc[2][2], double-buffered.
// ---------------------------------------------------------------------------
__global__ __launch_bounds__(256) void k4_out(const float* __restrict__ WO,
                                              float* __restrict__ out)
{
    __shared__ float as[32*33];
    __shared__ float bs[32*33];

    const int tid  = threadIdx.x;
    const int row0 = blockIdx.x * 32;
    const int col0 = blockIdx.y * 32;
    const int rt   = tid >> 4;
    const int jt   = tid & 15;

    float ra[4], rb[4];
    #pragma unroll
    for (int it = 0; it < 4; it++) {
        int i = tid + 256*it;
        ra[it] = g_hu[(size_t)(row0 + (i >> 5))*DD + (i & 31)];
        rb[it] = WO[(size_t)(col0 + (i >> 5))*DD + (i & 31)];
    }

    float acc[2][2] = {};
    for (int dc = 0; dc < DD; dc += 32) {
        __syncthreads();
        #pragma unroll
        for (int it = 0; it < 4; it++) {
            int i = tid + 256*it;
            as[(i >> 5)*33 + (i & 31)] = ra[it];
            bs[(i >> 5)*33 + (i & 31)] = rb[it];
        }
        __syncthreads();
        if (dc + 32 < DD) {
            #pragma unroll
            for (int it = 0; it < 4; it++) {
                int i = tid + 256*it;
                ra[it] = g_hu[(size_t)(row0 + (i >> 5))*DD + dc + 32 + (i & 31)];
                rb[it] = WO[(size_t)(col0 + (i >> 5))*DD + dc + 32 + (i & 31)];
            }
        }
        #pragma unroll
        for (int c = 0; c < 32; c++) {
            float a[2], b[2];
            #pragma unroll
            for (int m = 0; m < 2; m++) a[m] = as[(rt + 16*m)*33 + c];
            #pragma unroll
            for (int n = 0; n < 2; n++) b[n] = bs[(jt + 16*n)*33 + c];
            #pragma unroll
            for (int m = 0; m < 2; m++)
                #pragma unroll
                for (int n = 0; n < 2; n++) acc[m][n] += a[m]*b[n];
        }
    }
    #pragma unroll
    for (int m = 0; m < 2; m++)
        #pragma unroll
        for (int n = 0; n < 2; n++)
            out[(size_t)(row0 + rt + 16*m)*DD + col0 + jt + 16*n] = acc[m][n];
}

// ---------------------------------------------------------------------------
extern "C" void kernel_launch(void* const* d_in, const int* in_sizes, int n_in,
                              void* d_out, int out_size)
{
    const float* hV   = (const float*)d_in[0];
    const float* hE   = (const float*)d_in[1];
    const int*   mask = (const int*)  d_in[2];
    const float* WQ   = (const float*)d_in[3];
    const float* WK   = (const float*)d_in[4];
    const float* WV   = (const float*)d_in[5];
    const float* WO   = (const float*)d_in[6];
    float*       out  = (float*)d_out;

    kQQp   <<<dim3(ROWS/64, HH),  256>>>(hV, WQ, WK);
    k2_attn<<<ROWS,               256>>>(hE, mask);
    k3_vproj<<<dim3(ROWS/32, HH), 256>>>(WV);
    k4_out <<<dim3(ROWS/32, 4),   256>>>(WO, out);
}

// round 14
// speedup vs baseline: 1.1350x; 1.1350x over previous
#include <cuda_runtime.h>
#include <math.h>
#include <stdint.h>

// Problem constants
#define BB   4
#define NN   2000
#define KKN  30
#define DD   128
#define DIN  256
#define HH   4
#define ROWS (BB*NN)           // 8000

#define SCALE 0.17677669529663687f   // 1/sqrt(32)

#define EPITCH 260             // padded E row pitch (floats): conflict-free banks
#define QPITCH 260             // padded Q row pitch

// Scratch (static device globals: no runtime allocation)
__device__ float g_Qp  [(size_t)ROWS*HH*DIN];  // 32 MB  per-head K-projected query
__device__ float g_Eagg[(size_t)ROWS*HH*DIN];  // 32 MB  softmax-weighted E aggregate
__device__ float g_hu  [(size_t)ROWS*DD];      //  4 MB  per-head V projection

// ---------------------------------------------------------------------------
// Kernel QQp (fused, double-buffered): per head h, 64-row block.
//   Phase 1: Q_h[r][j] = sum_d hV[r][d] * WQ[h*32+j][d]     (into smem qs)
//   Phase 2: Qp[r][h*256+c] = SCALE * sum_j Q_h[r][j] * WK[h*32+j][c]
// grid (125, 4 heads), 256 threads.
// ---------------------------------------------------------------------------
__global__ __launch_bounds__(256) void kQQp(const float* __restrict__ hV,
                                            const float* __restrict__ WQ,
                                            const float* __restrict__ WK)
{
    __shared__ float as[64*33];    // hV chunk (64 x 32)
    __shared__ float bs[32*33];    // WQ chunk (32 j x 32 d)
    __shared__ float qs[64*33];    // Q_h tile (64 x 32)
    __shared__ float ws[32*65];    // WK chunk (32 j x 64 c)

    const int tid  = threadIdx.x;
    const int row0 = blockIdx.x * 64;
    const int h    = blockIdx.y;
    const int rt   = tid >> 4;   // 0..15
    const int jt   = tid & 15;   // 0..15

    // ---- Phase 1: Q_h = hV @ WQ_h^T (K=128, chunk 32), register prefetch
    float ra[8], rb[4];
    #pragma unroll
    for (int it = 0; it < 8; it++) {
        int i = tid + 256*it;
        ra[it] = hV[(size_t)(row0 + (i >> 5))*DD + (i & 31)];
    }
    #pragma unroll
    for (int it = 0; it < 4; it++) {
        int i = tid + 256*it;
        rb[it] = WQ[(size_t)(h*32 + (i >> 5))*DD + (i & 31)];
    }

    float acc[4][2] = {};
    for (int dc = 0; dc < DD; dc += 32) {
        __syncthreads();
        #pragma unroll
        for (int it = 0; it < 8; it++) {
            int i = tid + 256*it;
            as[(i >> 5)*33 + (i & 31)] = ra[it];
        }
        #pragma unroll
        for (int it = 0; it < 4; it++) {
            int i = tid + 256*it;
            bs[(i >> 5)*33 + (i & 31)] = rb[it];
        }
        __syncthreads();
        if (dc + 32 < DD) {
            #pragma unroll
            for (int it = 0; it < 8; it++) {
                int i = tid + 256*it;
                ra[it] = hV[(size_t)(row0 + (i >> 5))*DD + dc + 32 + (i & 31)];
            }
            #pragma unroll
            for (int it = 0; it < 4; it++) {
                int i = tid + 256*it;
                rb[it] = WQ[(size_t)(h*32 + (i >> 5))*DD + dc + 32 + (i & 31)];
            }
        }
        #pragma unroll
        for (int c = 0; c < 32; c++) {
            float a[4], b[2];
            #pragma unroll
            for (int m = 0; m < 4; m++) a[m] = as[(rt + 16*m)*33 + c];
            #pragma unroll
            for (int n = 0; n < 2; n++) b[n] = bs[(jt + 16*n)*33 + c];
            #pragma unroll
            for (int m = 0; m < 4; m++)
                #pragma unroll
                for (int n = 0; n < 2; n++) acc[m][n] += a[m]*b[n];
        }
    }
    __syncthreads();
    #pragma unroll
    for (int m = 0; m < 4; m++)
        #pragma unroll
        for (int n = 0; n < 2; n++)
            qs[(rt + 16*m)*33 + jt + 16*n] = acc[m][n];

    // ---- Phase 2: Qp = qs(64x32) @ WK_h(32x256), c chunked by 64, prefetch
    const int ct = tid & 15;
    float rw[8];
    #pragma unroll
    for (int it = 0; it < 8; it++) {
        int i = tid + 256*it;
        rw[it] = WK[(size_t)(h*32 + (i >> 6))*DIN + (i & 63)];
    }
    for (int cc = 0; cc < DIN; cc += 64) {
        __syncthreads();
        #pragma unroll
        for (int it = 0; it < 8; it++) {
            int i = tid + 256*it;
            ws[(i >> 6)*65 + (i & 63)] = rw[it];
        }
        __syncthreads();
        if (cc + 64 < DIN) {
            #pragma unroll
            for (int it = 0; it < 8; it++) {
                int i = tid + 256*it;
                rw[it] = WK[(size_t)(h*32 + (i >> 6))*DIN + cc + 64 + (i & 63)];
            }
        }
        float a2[4][4] = {};
        #pragma unroll
        for (int j = 0; j < 32; j++) {
            float a[4], b[4];
            #pragma unroll
            for (int m = 0; m < 4; m++) a[m] = qs[(rt + 16*m)*33 + j];
            #pragma unroll
            for (int n = 0; n < 4; n++) b[n] = ws[j*65 + ct + 16*n];
            #pragma unroll
            for (int m = 0; m < 4; m++)
                #pragma unroll
                for (int n = 0; n < 4; n++) a2[m][n] += a[m]*b[n];
        }
        #pragma unroll
        for (int m = 0; m < 4; m++)
            #pragma unroll
            for (int n = 0; n < 4; n++)
                g_Qp[(size_t)(row0 + rt + 16*m)*(HH*DIN) + h*DIN + cc + ct + 16*n]
                    = a2[m][n] * SCALE;
    }
}

// ---------------------------------------------------------------------------
// Kernel 2 (shuffle-free, split logits): one block per row, 256 threads.
// E tile loaded with explicit 8-deep LDG batch (full MLP), padded smem;
// logits = two 120-thread groups, half-dot each; masked softmax; aggregation.
// ---------------------------------------------------------------------------
__global__ __launch_bounds__(256) void k2_attn(const float* __restrict__ hE,
                                               const int*   __restrict__ mask)
{
    __shared__ __align__(16) float Es[KKN*EPITCH];  // 30x260
    __shared__ __align__(16) float Qs[HH*QPITCH];   // 4x260
    __shared__ float lp[2*120];                     // partial logits
    __shared__ __align__(16) float ws[32*4];        // [k][h]
    __shared__ int   ms[32];

    const int tid = threadIdx.x;
    const int row = blockIdx.x;

    // Loads: Qp + mask first, then E tile as 8-deep register batch -> smem
    {
        float4 qv;
        int    mv = 0;
        const bool hasq = (tid < (HH*DIN)/4);
        if (hasq) {
            const float4* Qg = (const float4*)(g_Qp + (size_t)row * (HH*DIN));
            qv = Qg[tid];
        }
        if (tid < KKN) mv = mask[row*KKN + tid];

        const float4* Eg = (const float4*)(hE + (size_t)row * (KKN*DIN));
        float4 ev[8];
        #pragma unroll
        for (int s = 0; s < 7; s++) ev[s] = Eg[tid + 256*s];
        if (tid < 1920 - 256*7) ev[7] = Eg[tid + 256*7];

        if (hasq) {
            int h = tid >> 6, c4 = tid & 63;
            *(float4*)&Qs[h*QPITCH + c4*4] = qv;
        }
        if (tid < KKN) ms[tid] = mv;
        #pragma unroll
        for (int s = 0; s < 7; s++) {
            int i = tid + 256*s;
            *(float4*)&Es[(i >> 6)*EPITCH + (i & 63)*4] = ev[s];
        }
        if (tid < 1920 - 256*7) {
            int i = tid + 256*7;
            *(float4*)&Es[(i >> 6)*EPITCH + (i & 63)*4] = ev[7];
        }
    }
    __syncthreads();

    // ---- logits: two groups, each thread does a 128-float private dot ----
    {
        const int grp = tid >> 7;          // 0 or 1
        const int t   = tid & 127;         // index within group
        if (t < 120) {
            const int k = t >> 2, h = t & 3;
            const float4* e4 = (const float4*)(Es + k*EPITCH) + grp*32;
            const float4* q4 = (const float4*)(Qs + h*QPITCH) + grp*32;
            float a0 = 0.f, a1 = 0.f, a2 = 0.f, a3 = 0.f;
            #pragma unroll
            for (int c = 0; c < 32; c += 4) {
                float4 e, q;
                e = e4[c+0]; q = q4[c+0]; a0 += e.x*q.x + e.y*q.y + e.z*q.z + e.w*q.w;
                e = e4[c+1]; q = q4[c+1]; a1 += e.x*q.x + e.y*q.y + e.z*q.z + e.w*q.w;
                e = e4[c+2]; q = q4[c+2]; a2 += e.x*q.x + e.y*q.y + e.z*q.z + e.w*q.w;
                e = e4[c+3]; q = q4[c+3]; a3 += e.x*q.x + e.y*q.y + e.z*q.z + e.w*q.w;
            }
            lp[grp*120 + t] = (a0 + a1) + (a2 + a3);
        }
    }
    __syncthreads();

    const int warp = tid >> 5, lane = tid & 31;

    // ---- masked softmax per head (one warp per head); combine partials here
    if (warp < HH) {
        int   m = 0;
        float v = -3.0e38f;
        if (lane < KKN) {
            m = ms[lane];
            int idx = lane*4 + warp;
            v = m ? (lp[idx] + lp[120 + idx]) : -3.0e38f;
        }
        float mx = v;
        #pragma unroll
        for (int off = 16; off; off >>= 1) mx = fmaxf(mx, __shfl_xor_sync(0xffffffffu, mx, off));
        float e   = (lane < KKN) ? expf(v - mx) : 0.f;
        float smv = e;
        #pragma unroll
        for (int off = 16; off; off >>= 1) smv += __shfl_xor_sync(0xffffffffu, smv, off);
        if (lane < KKN) ws[lane*4 + warp] = (e / smv) * (float)m;
    }
    __syncthreads();

    // ---- aggregation: Eagg[h][c] = sum_k w[k][h] * E[k][c] ----
    {
        const int c = tid;  // 0..255
        float acc0 = 0.f, acc1 = 0.f, acc2 = 0.f, acc3 = 0.f;
        #pragma unroll 5
        for (int k = 0; k < KKN; k++) {
            float4 w  = *(const float4*)&ws[k*4];
            float  ev = Es[k*EPITCH + c];
            acc0 += w.x * ev; acc1 += w.y * ev; acc2 += w.z * ev; acc3 += w.w * ev;
        }
        float* out = g_Eagg + (size_t)row * (HH*DIN);
        out[0*DIN + c] = acc0;
        out[1*DIN + c] = acc1;
        out[2*DIN + c] = acc2;
        out[3*DIN + c] = acc3;
    }
}

// ---------------------------------------------------------------------------
// Kernel 3: hu[r][h*32+j] = sum_c WV[h*32+j][c] * Eagg[r][h][c]
// 64 rows x 32 j (one head), 256 threads, acc[4][2], double-buffered.
// grid (125, 4 heads)   [R12 shape — near its smem-traffic floor]
// ---------------------------------------------------------------------------
__global__ __launch_bounds__(256) void k3_vproj(const float* __restrict__ WV)
{
    __shared__ float as[64*33];
    __shared__ float bs[32*33];

    const int tid  = threadIdx.x;
    const int row0 = blockIdx.x * 64;
    const int h    = blockIdx.y;
    const int rt   = tid >> 4;
    const int jt   = tid & 15;

    const float* A  = g_Eagg + (size_t)h * DIN;
    const float* Bw = WV + (size_t)h * 32 * DIN;

    float ra[8], rb[4];
    #pragma unroll
    for (int it = 0; it < 8; it++) {
        int i = tid + 256*it;
        ra[it] = A[(size_t)(row0 + (i >> 5))*(HH*DIN) + (i & 31)];
    }
    #pragma unroll
    for (int it = 0; it < 4; it++) {
        int i = tid + 256*it;
        rb[it] = Bw[(size_t)(i >> 5)*DIN + (i & 31)];
    }

    float acc[4][2] = {};
    for (int cc = 0; cc < DIN; cc += 32) {
        __syncthreads();
        #pragma unroll
        for (int it = 0; it < 8; it++) {
            int i = tid + 256*it;
            as[(i >> 5)*33 + (i & 31)] = ra[it];
        }
        #pragma unroll
        for (int it = 0; it < 4; it++) {
            int i = tid + 256*it;
            bs[(i >> 5)*33 + (i & 31)] = rb[it];
        }
        __syncthreads();
        if (cc + 32 < DIN) {
            #pragma unroll
            for (int it = 0; it < 8; it++) {
                int i = tid + 256*it;
                ra[it] = A[(size_t)(row0 + (i >> 5))*(HH*DIN) + cc + 32 + (i & 31)];
            }
            #pragma unroll
            for (int it = 0; it < 4; it++) {
                int i = tid + 256*it;
                rb[it] = Bw[(size_t)(i >> 5)*DIN + cc + 32 + (i & 31)];
            }
        }
        #pragma unroll
        for (int c = 0; c < 32; c++) {
            float a[4], b[2];
            #pragma unroll
            for (int m = 0; m < 4; m++) a[m] = as[(rt + 16*m)*33 + c];
            #pragma unroll
            for (int n = 0; n < 2; n++) b[n] = bs[(jt + 16*n)*33 + c];
            #pragma unroll
            for (int m = 0; m < 4; m++)
                #pragma unroll
                for (int n = 0; n < 2; n++) acc[m][n] += a[m]*b[n];
        }
    }
    #pragma unroll
    for (int m = 0; m < 4; m++)
        #pragma unroll
        for (int n = 0; n < 2; n++)
            g_hu[(size_t)(row0 + rt + 16*m)*DD + h*32 + jt + 16*n] = acc[m][n];
}

// ---------------------------------------------------------------------------
// Kernel 4: out[r][o] = sum_d hu[r][d] * WO[o][d]
// 64 rows x 32 cols, grid (125, 4), acc[4][2], double-buffered. [R12 shape]
// ---------------------------------------------------------------------------
__global__ __launch_bounds__(256) void k4_out(const float* __restrict__ WO,
                                              float* __restrict__ out)
{
    __shared__ float as[64*33];
    __shared__ float bs[32*33];

    const int tid  = threadIdx.x;
    const int row0 = blockIdx.x * 64;
    const int col0 = blockIdx.y * 32;
    const int rt   = tid >> 4;
    const int jt   = tid & 15;

    float ra[8], rb[4];
    #pragma unroll
    for (int it = 0; it < 8; it++) {
        int i = tid + 256*it;
        ra[it] = g_hu[(size_t)(row0 + (i >> 5))*DD + (i & 31)];
    }
    #pragma unroll
    for (int it = 0; it < 4; it++) {
        int i = tid + 256*it;
        rb[it] = WO[(size_t)(col0 + (i >> 5))*DD + (i & 31)];
    }

    float acc[4][2] = {};
    for (int dc = 0; dc < DD; dc += 32) {
        __syncthreads();
        #pragma unroll
        for (int it = 0; it < 8; it++) {
            int i = tid + 256*it;
            as[(i >> 5)*33 + (i & 31)] = ra[it];
        }
        #pragma unroll
        for (int it = 0; it < 4; it++) {
            int i = tid + 256*it;
            bs[(i >> 5)*33 + (i & 31)] = rb[it];
        }
        __syncthreads();
        if (dc + 32 < DD) {
            #pragma unroll
            for (int it = 0; it < 8; it++) {
                int i = tid + 256*it;
                ra[it] = g_hu[(size_t)(row0 + (i >> 5))*DD + dc + 32 + (i & 31)];
            }
            #pragma unroll
            for (int it = 0; it < 4; it++) {
                int i = tid + 256*it;
                rb[it] = WO[(size_t)(col0 + (i >> 5))*DD + dc + 32 + (i & 31)];
            }
        }
        #pragma unroll
        for (int c = 0; c < 32; c++) {
            float a[4], b[2];
            #pragma unroll
            for (int m = 0; m < 4; m++) a[m] = as[(rt + 16*m)*33 + c];
            #pragma unroll
            for (int n = 0; n < 2; n++) b[n] = bs[(jt + 16*n)*33 + c];
            #pragma unroll
            for (int m = 0; m < 4; m++)
                #pragma unroll
                for (int n = 0; n < 2; n++) acc[m][n] += a[m]*b[n];
        }
    }
    #pragma unroll
    for (int m = 0; m < 4; m++)
        #pragma unroll
        for (int n = 0; n < 2; n++)
            out[(size_t)(row0 + rt + 16*m)*DD + col0 + jt + 16*n] = acc[m][n];
}

// ---------------------------------------------------------------------------
extern "C" void kernel_launch(void* const* d_in, const int* in_sizes, int n_in,
                              void* d_out, int out_size)
{
    const float* hV   = (const float*)d_in[0];
    const float* hE   = (const float*)d_in[1];
    const int*   mask = (const int*)  d_in[2];
    const float* WQ   = (const float*)d_in[3];
    const float* WK   = (const float*)d_in[4];
    const float* WV   = (const float*)d_in[5];
    const float* WO   = (const float*)d_in[6];
    float*       out  = (float*)d_out;

    kQQp   <<<dim3(ROWS/64, HH),  256>>>(hV, WQ, WK);
    k2_attn<<<ROWS,               256>>>(hE, mask);
    k3_vproj<<<dim3(ROWS/64, HH), 256>>>(WV);
    k4_out <<<dim3(ROWS/64, 4),   256>>>(WO, out);
}